// round 16
// baseline (speedup 1.0000x reference)
#include <cuda_runtime.h>
#include <cstdint>

#define NT       4096
#define NTRACES  512
#define CHANNELS 8
#define COLS     (NTRACES * CHANNELS)   // 4096
#define THREADS  512
#define WARPS    16
#define IPT      8                      // 512*8 = 4096
#define NBINS    2048                   // per plane; 4 planes (pairs 0/1,2/3,4/5,6/7)
#define NBLOCKS  NTRACES                // one trace (8 channels) per block

#define BIN_SCALE (2048.0f / 12.0f)
#define BINW      (12.0f / 2048.0f)

// dp4a byte-coefficient masks (signed bytes, little-endian B0..B3)
#define C_D0 ((int)0x0000FF01)   // +1, -1,  0,  0  -> B0 - B1  (even pair: pred - obs)
#define C_D1 ((int)0xFF010000)   //  0,  0, +1, -1  -> B2 - B3  (odd  pair: pred - obs)

__device__ float        g_partials[NBLOCKS];
__device__ unsigned int g_done = 0;

__device__ __forceinline__ int bin_of(float v) {
    int b = __float2int_rd(fmaf(v, BIN_SCALE, 6.0f * BIN_SCALE));
    return min(max(b, 0), NBINS - 1);
}

// Scan one 2048-word plane (two packed pairs). Each warp owns exactly 32 uint4
// (128 words), lane-consecutive. Returns this thread's integer share of
// sum_b (|cumPe-cumOe| + |cumPo-cumOo|). Caller barriers around is0/is1 reuse.
__device__ __forceinline__ int scan_plane(const unsigned* __restrict__ Hp,
                                          int* __restrict__ is0,
                                          int* __restrict__ is1,
                                          int lane, int wid)
{
    const uint4 w = reinterpret_cast<const uint4*>(Hp)[wid * 32 + lane];

    int d0 = __dp4a((int)w.x, C_D0, 0); d0 = __dp4a((int)w.y, C_D0, d0);
    d0 = __dp4a((int)w.z, C_D0, d0);    d0 = __dp4a((int)w.w, C_D0, d0);
    int d1 = __dp4a((int)w.x, C_D1, 0); d1 = __dp4a((int)w.y, C_D1, d1);
    d1 = __dp4a((int)w.z, C_D1, d1);    d1 = __dp4a((int)w.w, C_D1, d1);

    int x0 = d0, x1 = d1;
    #pragma unroll
    for (int off = 1; off < 32; off <<= 1) {
        int y0 = __shfl_up_sync(0xFFFFFFFFu, x0, off);
        int y1 = __shfl_up_sync(0xFFFFFFFFu, x1, off);
        if (lane >= off) { x0 += y0; x1 += y1; }
    }
    if (lane == 31) { is0[wid] = x0; is1[wid] = x1; }
    __syncthreads();
    if (wid == 0) {
        int s0 = (lane < WARPS) ? is0[lane] : 0;
        int s1 = (lane < WARPS) ? is1[lane] : 0;
        #pragma unroll
        for (int off = 1; off < WARPS; off <<= 1) {
            int y0 = __shfl_up_sync(0xFFFFFFFFu, s0, off);
            int y1 = __shfl_up_sync(0xFFFFFFFFu, s1, off);
            if (lane >= off) { s0 += y0; s1 += y1; }
        }
        if (lane < WARPS) { is0[lane] = s0; is1[lane] = s1; }
    }
    __syncthreads();

    // cum entering this lane's 4 words (exclusive)
    int c0c = (wid ? is0[wid - 1] : 0) + x0 - d0;
    int c1c = (wid ? is1[wid - 1] : 0) + x1 - d1;

    int a = 0;
    #pragma unroll
    for (int c = 0; c < 4; ++c) {
        unsigned u = (c == 0) ? w.x : (c == 1) ? w.y : (c == 2) ? w.z : w.w;
        c0c += __dp4a((int)u, C_D0, 0);  a += abs(c0c);
        c1c += __dp4a((int)u, C_D1, 0);  a += abs(c1c);
    }
    return a;
}

// Dynamic smem: 4 planes x 2048 words = 32KB, 4 blocks/SM
__global__ __launch_bounds__(THREADS, 4)
void wass_hist5_kernel(const float* __restrict__ pred,
                       const float* __restrict__ obs,
                       float* __restrict__ out)
{
    extern __shared__ unsigned H[];   // [4 * NBINS]

    __shared__ int    is0[WARPS], is1[WARPS];
    __shared__ float  sred[WARPS];
    __shared__ double dred[WARPS];
    __shared__ bool   s_last;

    const int tid  = threadIdx.x;
    const int lane = tid & 31;
    const int wid  = tid >> 5;
    const int base = blockIdx.x * CHANNELS;   // trace start (8 contiguous floats)

    // ---- zero all planes (8192 words = 2048 uint4 = 4/thread) ----
    #pragma unroll
    for (int k = 0; k < 4; ++k)
        reinterpret_cast<uint4*>(H)[tid + k * THREADS] = make_uint4(0u, 0u, 0u, 0u);
    __syncthreads();

    // ---- histogram: 4x float4 (full 32B sectors), consume immediately ----
    #pragma unroll
    for (int k = 0; k < IPT; ++k) {
        const size_t off = (size_t)(tid + k * THREADS) * COLS + base;
        float4 pa = __ldg(reinterpret_cast<const float4*>(pred + off));
        float4 pb = __ldg(reinterpret_cast<const float4*>(pred + off + 4));
        float4 oa = __ldg(reinterpret_cast<const float4*>(obs  + off));
        float4 ob = __ldg(reinterpret_cast<const float4*>(obs  + off + 4));
        // plane 0: channels 0 (x) / 1 (y)
        atomicAdd(&H[bin_of(pa.x)], 1u);
        atomicAdd(&H[bin_of(oa.x)], 0x100u);
        atomicAdd(&H[bin_of(pa.y)], 0x10000u);
        atomicAdd(&H[bin_of(oa.y)], 0x1000000u);
        // plane 1: channels 2 (z) / 3 (w)
        atomicAdd(&H[NBINS     + bin_of(pa.z)], 1u);
        atomicAdd(&H[NBINS     + bin_of(oa.z)], 0x100u);
        atomicAdd(&H[NBINS     + bin_of(pa.w)], 0x10000u);
        atomicAdd(&H[NBINS     + bin_of(oa.w)], 0x1000000u);
        // plane 2: channels 4 (x) / 5 (y)
        atomicAdd(&H[2 * NBINS + bin_of(pb.x)], 1u);
        atomicAdd(&H[2 * NBINS + bin_of(ob.x)], 0x100u);
        atomicAdd(&H[2 * NBINS + bin_of(pb.y)], 0x10000u);
        atomicAdd(&H[2 * NBINS + bin_of(ob.y)], 0x1000000u);
        // plane 3: channels 6 (z) / 7 (w)
        atomicAdd(&H[3 * NBINS + bin_of(pb.z)], 1u);
        atomicAdd(&H[3 * NBINS + bin_of(ob.z)], 0x100u);
        atomicAdd(&H[3 * NBINS + bin_of(pb.w)], 0x10000u);
        atomicAdd(&H[3 * NBINS + bin_of(ob.w)], 0x1000000u);
    }
    __syncthreads();

    // ---- scan 4 planes (8 column pairs total) ----
    int a = scan_plane(H,             is0, is1, lane, wid);
    __syncthreads();
    a +=    scan_plane(H + NBINS,     is0, is1, lane, wid);
    __syncthreads();
    a +=    scan_plane(H + 2 * NBINS, is0, is1, lane, wid);
    __syncthreads();
    a +=    scan_plane(H + 3 * NBINS, is0, is1, lane, wid);

    float acc = (float)a * BINW;

    // ---- deterministic block reduction ----
    #pragma unroll
    for (int off = 16; off > 0; off >>= 1)
        acc += __shfl_xor_sync(0xFFFFFFFFu, acc, off);
    if (lane == 0) sred[wid] = acc;
    __syncthreads();

    if (wid == 0) {
        float v = (lane < WARPS) ? sred[lane] : 0.0f;
        #pragma unroll
        for (int off = 8; off > 0; off >>= 1)
            v += __shfl_xor_sync(0xFFFFFFFFu, v, off);
        if (lane == 0) g_partials[blockIdx.x] = v;
    }

    // ---- last-block-done fused finalize (deterministic) ----
    if (tid == 0) {
        __threadfence();
        unsigned int t = atomicAdd(&g_done, 1u);
        s_last = (t == NBLOCKS - 1);
    }
    __syncthreads();

    if (s_last) {
        __threadfence();
        double d = 0.0;
        for (int i = tid; i < NBLOCKS; i += THREADS)
            d += (double)g_partials[i];
        #pragma unroll
        for (int off = 16; off > 0; off >>= 1)
            d += __shfl_xor_sync(0xFFFFFFFFu, d, off);
        if (lane == 0) dred[wid] = d;
        __syncthreads();
        if (wid == 0) {
            double v = (lane < WARPS) ? dred[lane] : 0.0;
            #pragma unroll
            for (int off = 8; off > 0; off >>= 1)
                v += __shfl_xor_sync(0xFFFFFFFFu, v, off);
            if (lane == 0) {
                out[0] = (float)(v / ((double)NT * (double)COLS));
                g_done = 0;   // reset for next graph replay
            }
        }
    }
}

extern "C" void kernel_launch(void* const* d_in, const int* in_sizes, int n_in,
                              void* d_out, int out_size)
{
    const float* pred = (const float*)d_in[0];
    const float* obs  = (const float*)d_in[1];
    float* out = (float*)d_out;

    const size_t smem_bytes = 4 * NBINS * sizeof(unsigned);   // 32KB
    cudaFuncSetAttribute(wass_hist5_kernel,
                         cudaFuncAttributeMaxDynamicSharedMemorySize,
                         (int)smem_bytes);

    wass_hist5_kernel<<<NBLOCKS, THREADS, smem_bytes>>>(pred, obs, out);
}

// round 17
// speedup vs baseline: 1.1796x; 1.1796x over previous
#include <cuda_runtime.h>
#include <cstdint>

#define NT       4096
#define NTRACES  512
#define CHANNELS 8
#define COLS     (NTRACES * CHANNELS)   // 4096
#define THREADS  512
#define WARPS    16
#define IPT      8                      // 512*8 = 4096
#define NBINS    2048                   // per plane; 2 planes (pairs 0/1 and 2/3)
#define CH_PER_BLK 4
#define NBLOCKS  (NTRACES * (CHANNELS / CH_PER_BLK))  // 1024

#define BIN_SCALE (2048.0f / 12.0f)
#define BINW      (12.0f / 2048.0f)

// dp4a byte-coefficient masks (signed bytes, little-endian B0..B3)
#define C_D0 ((int)0x0000FF01)   // +1, -1,  0,  0  -> B0 - B1  (even pair: pred - obs)
#define C_D1 ((int)0xFF010000)   //  0,  0, +1, -1  -> B2 - B3  (odd  pair: pred - obs)

__device__ float        g_partials[NBLOCKS];
__device__ unsigned int g_done = 0;

__device__ __forceinline__ int bin_of(float v) {
    int b = __float2int_rd(fmaf(v, BIN_SCALE, 6.0f * BIN_SCALE));
    return min(max(b, 0), NBINS - 1);
}

// Scan one 2048-word plane (two packed pairs). Each warp owns exactly 32 uint4
// (128 words), lane-consecutive. Returns this thread's integer share of
// sum_b (|cumPe-cumOe| + |cumPo-cumOo|). Caller barriers around is0/is1 reuse.
__device__ __forceinline__ int scan_plane(const unsigned* __restrict__ Hp,
                                          int* __restrict__ is0,
                                          int* __restrict__ is1,
                                          int lane, int wid)
{
    const uint4 w = reinterpret_cast<const uint4*>(Hp)[wid * 32 + lane];

    int d0 = __dp4a((int)w.x, C_D0, 0); d0 = __dp4a((int)w.y, C_D0, d0);
    d0 = __dp4a((int)w.z, C_D0, d0);    d0 = __dp4a((int)w.w, C_D0, d0);
    int d1 = __dp4a((int)w.x, C_D1, 0); d1 = __dp4a((int)w.y, C_D1, d1);
    d1 = __dp4a((int)w.z, C_D1, d1);    d1 = __dp4a((int)w.w, C_D1, d1);

    int x0 = d0, x1 = d1;
    #pragma unroll
    for (int off = 1; off < 32; off <<= 1) {
        int y0 = __shfl_up_sync(0xFFFFFFFFu, x0, off);
        int y1 = __shfl_up_sync(0xFFFFFFFFu, x1, off);
        if (lane >= off) { x0 += y0; x1 += y1; }
    }
    if (lane == 31) { is0[wid] = x0; is1[wid] = x1; }
    __syncthreads();
    if (wid == 0) {
        int s0 = (lane < WARPS) ? is0[lane] : 0;
        int s1 = (lane < WARPS) ? is1[lane] : 0;
        #pragma unroll
        for (int off = 1; off < WARPS; off <<= 1) {
            int y0 = __shfl_up_sync(0xFFFFFFFFu, s0, off);
            int y1 = __shfl_up_sync(0xFFFFFFFFu, s1, off);
            if (lane >= off) { s0 += y0; s1 += y1; }
        }
        if (lane < WARPS) { is0[lane] = s0; is1[lane] = s1; }
    }
    __syncthreads();

    // cum entering this lane's 4 words (exclusive)
    int c0c = (wid ? is0[wid - 1] : 0) + x0 - d0;
    int c1c = (wid ? is1[wid - 1] : 0) + x1 - d1;

    int a = 0;
    #pragma unroll
    for (int c = 0; c < 4; ++c) {
        unsigned u = (c == 0) ? w.x : (c == 1) ? w.y : (c == 2) ? w.z : w.w;
        c0c += __dp4a((int)u, C_D0, 0);  a += abs(c0c);
        c1c += __dp4a((int)u, C_D1, 0);  a += abs(c1c);
    }
    return a;
}

// Dynamic smem: 2 planes x 2048 words = 16KB, 4 blocks/SM (thread-capped)
__global__ __launch_bounds__(THREADS, 4)
void wass_hist6_kernel(const float* __restrict__ pred,
                       const float* __restrict__ obs,
                       float* __restrict__ out)
{
    extern __shared__ unsigned H[];   // [2 * NBINS]

    __shared__ int    is0[WARPS], is1[WARPS];
    __shared__ float  sred[WARPS];
    __shared__ double dred[WARPS];
    __shared__ bool   s_last;

    const int tid  = threadIdx.x;
    const int lane = tid & 31;
    const int wid  = tid >> 5;
    const int tr   = blockIdx.x >> 1;               // trace
    const int c0   = (blockIdx.x & 1) * CH_PER_BLK; // channel base (0 or 4)
    const int base = tr * CHANNELS + c0;

    // ---- zero both planes (4096 words = 1024 uint4 = 2/thread) ----
    #pragma unroll
    for (int k = 0; k < 2; ++k)
        reinterpret_cast<uint4*>(H)[tid + k * THREADS] = make_uint4(0u, 0u, 0u, 0u);
    __syncthreads();

    // ---- histogram: float4 loads, consume immediately (1 atomic/element) ----
    #pragma unroll
    for (int k = 0; k < IPT; ++k) {
        const size_t off = (size_t)(tid + k * THREADS) * COLS + base;
        float4 p = __ldg(reinterpret_cast<const float4*>(pred + off));
        float4 o = __ldg(reinterpret_cast<const float4*>(obs  + off));
        // plane 0: channels c0+0 (x) / c0+1 (y)
        atomicAdd(&H[bin_of(p.x)], 1u);
        atomicAdd(&H[bin_of(o.x)], 0x100u);
        atomicAdd(&H[bin_of(p.y)], 0x10000u);
        atomicAdd(&H[bin_of(o.y)], 0x1000000u);
        // plane 1: channels c0+2 (z) / c0+3 (w)
        atomicAdd(&H[NBINS + bin_of(p.z)], 1u);
        atomicAdd(&H[NBINS + bin_of(o.z)], 0x100u);
        atomicAdd(&H[NBINS + bin_of(p.w)], 0x10000u);
        atomicAdd(&H[NBINS + bin_of(o.w)], 0x1000000u);
    }
    __syncthreads();

    // ---- scan both planes (4 column pairs total) ----
    int a = scan_plane(H, is0, is1, lane, wid);
    __syncthreads();                  // is0/is1 reuse
    a += scan_plane(H + NBINS, is0, is1, lane, wid);

    float acc = (float)a * BINW;

    // ---- deterministic block reduction ----
    #pragma unroll
    for (int off = 16; off > 0; off >>= 1)
        acc += __shfl_xor_sync(0xFFFFFFFFu, acc, off);
    if (lane == 0) sred[wid] = acc;
    __syncthreads();

    if (wid == 0) {
        float v = (lane < WARPS) ? sred[lane] : 0.0f;
        #pragma unroll
        for (int off = 8; off > 0; off >>= 1)
            v += __shfl_xor_sync(0xFFFFFFFFu, v, off);
        if (lane == 0) g_partials[blockIdx.x] = v;
    }

    // ---- last-block-done fused finalize (deterministic) ----
    if (tid == 0) {
        __threadfence();
        unsigned int t = atomicAdd(&g_done, 1u);
        s_last = (t == NBLOCKS - 1);
    }
    __syncthreads();

    if (s_last) {
        __threadfence();
        double d = 0.0;
        for (int i = tid; i < NBLOCKS; i += THREADS)
            d += (double)g_partials[i];
        #pragma unroll
        for (int off = 16; off > 0; off >>= 1)
            d += __shfl_xor_sync(0xFFFFFFFFu, d, off);
        if (lane == 0) dred[wid] = d;
        __syncthreads();
        if (wid == 0) {
            double v = (lane < WARPS) ? dred[lane] : 0.0;
            #pragma unroll
            for (int off = 8; off > 0; off >>= 1)
                v += __shfl_xor_sync(0xFFFFFFFFu, v, off);
            if (lane == 0) {
                out[0] = (float)(v / ((double)NT * (double)COLS));
                g_done = 0;   // reset for next graph replay
            }
        }
    }
}

extern "C" void kernel_launch(void* const* d_in, const int* in_sizes, int n_in,
                              void* d_out, int out_size)
{
    const float* pred = (const float*)d_in[0];
    const float* obs  = (const float*)d_in[1];
    float* out = (float*)d_out;

    const size_t smem_bytes = 2 * NBINS * sizeof(unsigned);   // 16KB
    cudaFuncSetAttribute(wass_hist6_kernel,
                         cudaFuncAttributeMaxDynamicSharedMemorySize,
                         (int)smem_bytes);

    wass_hist6_kernel<<<NBLOCKS, THREADS, smem_bytes>>>(pred, obs, out);
}